// round 3
// baseline (speedup 1.0000x reference)
#include <cuda_runtime.h>
#include <math.h>

// Problem dims (fixed)
#define BB   2
#define TT   2048
#define CC   1024
#define HH   16
#define DD   64
#define HID  256
#define FF   4096
#define MM   (BB*TT)   // 4096 rows

// ---------------- scratch (device globals; no allocation allowed) ----------------
__device__ __align__(16) float g_q [MM*CC];
__device__ __align__(16) float g_k [MM*CC];
__device__ __align__(16) float g_v [MM*CC];
__device__ __align__(16) float g_h [MM*HID];
__device__ __align__(16) float g_sur[MM*HH];
__device__ __align__(16) float g_ys[MM*CC];
__device__ __align__(16) float g_y [MM*CC];
__device__ __align__(16) float g_yn[MM*CC];
__device__ __align__(16) float g_ff[MM*FF];

// ---------------- tiled SGEMM: out[M,N] = epilogue( A[M,K] @ W[N,K]^T ) ----------
// EPI: 0 = plain, 1 = relu(acc + bias[n]), 2 = relu(acc)^2, 3 = acc + R[m,n]
#define BMT 64
#define BNT 64
#define BKT 16

template<int EPI>
__global__ __launch_bounds__(256) void sgemm_kernel(
    const float* __restrict__ A, const float* __restrict__ W,
    const float* __restrict__ bias, const float* __restrict__ R,
    float* __restrict__ out, int M, int N, int K)
{
    __shared__ float As[BKT][BMT];
    __shared__ float Bs[BKT][BNT];

    const int block_m = blockIdx.y * BMT;
    const int block_n = blockIdx.x * BNT;
    const int tid = threadIdx.x;          // 0..255
    const int tx = tid & 15;              // 0..15
    const int ty = tid >> 4;              // 0..15
    const int lm = tid >> 2;              // 0..63 : row within tile to load
    const int lk = (tid & 3) * 4;         // 0,4,8,12 : k offset (float4)

    float acc[4][4];
#pragma unroll
    for (int i = 0; i < 4; i++)
#pragma unroll
        for (int j = 0; j < 4; j++) acc[i][j] = 0.f;

    const float* aPtr = A + (size_t)(block_m + lm) * K + lk;
    const float* bPtr = W + (size_t)(block_n + lm) * K + lk;

    for (int k0 = 0; k0 < K; k0 += BKT) {
        float4 av = *(const float4*)(aPtr + k0);
        float4 bv = *(const float4*)(bPtr + k0);
        As[lk + 0][lm] = av.x; As[lk + 1][lm] = av.y;
        As[lk + 2][lm] = av.z; As[lk + 3][lm] = av.w;
        Bs[lk + 0][lm] = bv.x; Bs[lk + 1][lm] = bv.y;
        Bs[lk + 2][lm] = bv.z; Bs[lk + 3][lm] = bv.w;
        __syncthreads();

#pragma unroll
        for (int kk = 0; kk < BKT; kk++) {
            float4 a = *(const float4*)&As[kk][ty * 4];
            float4 b = *(const float4*)&Bs[kk][tx * 4];
            acc[0][0] += a.x * b.x; acc[0][1] += a.x * b.y; acc[0][2] += a.x * b.z; acc[0][3] += a.x * b.w;
            acc[1][0] += a.y * b.x; acc[1][1] += a.y * b.y; acc[1][2] += a.y * b.z; acc[1][3] += a.y * b.w;
            acc[2][0] += a.z * b.x; acc[2][1] += a.z * b.y; acc[2][2] += a.z * b.z; acc[2][3] += a.z * b.w;
            acc[3][0] += a.w * b.x; acc[3][1] += a.w * b.y; acc[3][2] += a.w * b.z; acc[3][3] += a.w * b.w;
        }
        __syncthreads();
    }

    // epilogue: one float4 store per row of the 4x4 micro-tile
    const int n0 = block_n + tx * 4;
    float4 bv4 = make_float4(0.f, 0.f, 0.f, 0.f);
    if (EPI == 1) bv4 = *(const float4*)(bias + n0);
#pragma unroll
    for (int i = 0; i < 4; i++) {
        const int m = block_m + ty * 4 + i;
        float4 o;
        o.x = acc[i][0]; o.y = acc[i][1]; o.z = acc[i][2]; o.w = acc[i][3];
        if (EPI == 1) {
            o.x = fmaxf(o.x + bv4.x, 0.f); o.y = fmaxf(o.y + bv4.y, 0.f);
            o.z = fmaxf(o.z + bv4.z, 0.f); o.w = fmaxf(o.w + bv4.w, 0.f);
        } else if (EPI == 2) {
            o.x = fmaxf(o.x, 0.f); o.x *= o.x;
            o.y = fmaxf(o.y, 0.f); o.y *= o.y;
            o.z = fmaxf(o.z, 0.f); o.z *= o.z;
            o.w = fmaxf(o.w, 0.f); o.w *= o.w;
        } else if (EPI == 3) {
            float4 r = *(const float4*)(R + (size_t)m * N + n0);
            o.x += r.x; o.y += r.y; o.z += r.z; o.w += r.w;
        }
        *(float4*)(out + (size_t)m * N + n0) = o;
    }
}

// ---------------- meta-net layer 2 + sigmoid: surprise[m,h] -----------------------
__global__ __launch_bounds__(256) void meta2_kernel(
    const float* __restrict__ hbuf, const float* __restrict__ Wm2,
    const float* __restrict__ bm2, float* __restrict__ sur)
{
    int idx = blockIdx.x * blockDim.x + threadIdx.x;   // over MM*HH
    if (idx >= MM * HH) return;
    int m = idx / HH, h = idx % HH;
    const float* hv = hbuf + (size_t)m * HID;
    const float* w  = Wm2 + (size_t)h * HID;
    float acc = bm2[h];
#pragma unroll 8
    for (int j = 0; j < HID; j++) acc += hv[j] * w[j];
    sur[idx] = 1.f / (1.f + expf(-acc));
}

// ---------------- sequential gated linear-attention scan --------------------------
// state[d][e] per (b,h); thread e owns column e (64 regs). 32 blocks x 64 threads.
__global__ __launch_bounds__(64) void scan_kernel(
    const float* __restrict__ q, const float* __restrict__ k,
    const float* __restrict__ v, const float* __restrict__ sur,
    float* __restrict__ ys)
{
    const int bh = blockIdx.x;
    const int b = bh / HH, h = bh % HH;
    const int e = threadIdx.x;

    __shared__ float sk[DD];
    __shared__ float sq[DD];

    float s[DD];
#pragma unroll
    for (int d = 0; d < DD; d++) s[d] = 0.f;

    const size_t baseBT = (size_t)b * TT * CC + (size_t)h * DD;
    const int surBase = b * TT * HH + h;

    for (int t = 0; t < TT; t++) {
        const size_t off = baseBT + (size_t)t * CC;
        sk[e] = k[off + e];
        sq[e] = q[off + e];
        const float ve = v[off + e];
        const float g  = sur[surBase + t * HH];
        const float dt = 1.f - g;
        __syncthreads();

        const float c = g * ve;
        float accum = 0.f;
#pragma unroll
        for (int d = 0; d < DD; d++) {
            s[d] = s[d] * dt + c * sk[d];
            accum += sq[d] * s[d];
        }
        ys[off + e] = accum;
        __syncthreads();
    }
}

// ---------------- RMSNorm over last dim (C=1024) ----------------------------------
__global__ __launch_bounds__(256) void rmsnorm_kernel(
    const float* __restrict__ y, float* __restrict__ yn)
{
    const int row = blockIdx.x;
    const float* p = y + (size_t)row * CC;
    float ss = 0.f;
    for (int i = threadIdx.x; i < CC; i += 256) { float u = p[i]; ss += u * u; }

    // block reduction
    __shared__ float red[8];
    for (int o = 16; o > 0; o >>= 1) ss += __shfl_xor_sync(0xFFFFFFFF, ss, o);
    if ((threadIdx.x & 31) == 0) red[threadIdx.x >> 5] = ss;
    __syncthreads();
    if (threadIdx.x < 8) {
        ss = red[threadIdx.x];
        for (int o = 4; o > 0; o >>= 1) ss += __shfl_xor_sync(0xFF, ss, o);
        if (threadIdx.x == 0) red[0] = ss;
    }
    __syncthreads();
    const float inv = rsqrtf(red[0] * (1.f / CC) + 1.1920928955078125e-07f);
    for (int i = threadIdx.x; i < CC; i += 256)
        yn[(size_t)row * CC + i] = p[i] * inv;
}

// ---------------- host driver -----------------------------------------------------
extern "C" void kernel_launch(void* const* d_in, const int* in_sizes, int n_in,
                              void* d_out, int out_size)
{
    const float* x     = (const float*)d_in[0];
    const float* Wq    = (const float*)d_in[1];
    const float* Wk    = (const float*)d_in[2];
    const float* Wv    = (const float*)d_in[3];
    const float* Wm1   = (const float*)d_in[4];
    const float* bm1   = (const float*)d_in[5];
    const float* Wm2   = (const float*)d_in[6];
    const float* bm2   = (const float*)d_in[7];
    const float* Wproj = (const float*)d_in[8];
    const float* Wfc   = (const float*)d_in[9];
    const float* Wcp   = (const float*)d_in[10];
    float* out = (float*)d_out;

    float *pq, *pk, *pv, *ph, *psur, *pys, *py, *pyn, *pff;
    cudaGetSymbolAddress((void**)&pq,  g_q);
    cudaGetSymbolAddress((void**)&pk,  g_k);
    cudaGetSymbolAddress((void**)&pv,  g_v);
    cudaGetSymbolAddress((void**)&ph,  g_h);
    cudaGetSymbolAddress((void**)&psur,g_sur);
    cudaGetSymbolAddress((void**)&pys, g_ys);
    cudaGetSymbolAddress((void**)&py,  g_y);
    cudaGetSymbolAddress((void**)&pyn, g_yn);
    cudaGetSymbolAddress((void**)&pff, g_ff);

    dim3 thr(256);
    dim3 gC (CC  / BNT, MM / BMT);   // N=1024
    dim3 gH (HID / BNT, MM / BMT);   // N=256
    dim3 gFF(FF  / BNT, MM / BMT);   // N=4096

    // QKV projections
    sgemm_kernel<0><<<gC, thr>>>(x, Wq, nullptr, nullptr, pq, MM, CC, CC);
    sgemm_kernel<0><<<gC, thr>>>(x, Wk, nullptr, nullptr, pk, MM, CC, CC);
    sgemm_kernel<0><<<gC, thr>>>(x, Wv, nullptr, nullptr, pv, MM, CC, CC);

    // meta net: h = relu(x Wm1^T + bm1); surprise = sigmoid(h Wm2^T + bm2)
    sgemm_kernel<1><<<gH, thr>>>(x, Wm1, bm1, nullptr, ph, MM, HID, CC);
    meta2_kernel<<<(MM * HH + 255) / 256, thr>>>(ph, Wm2, bm2, psur);

    // gated linear-attention scan
    scan_kernel<<<BB * HH, DD>>>(pq, pk, pv, psur, pys);

    // output projection
    sgemm_kernel<0><<<gC, thr>>>(pys, Wproj, nullptr, nullptr, py, MM, CC, CC);

    // RMSNorm
    rmsnorm_kernel<<<MM, thr>>>(py, pyn);

    // MLP: ff = relu(yn Wfc^T)^2 ; out = y + ff Wcp^T
    sgemm_kernel<2><<<gFF, thr>>>(pyn, Wfc, nullptr, nullptr, pff, MM, FF, CC);
    sgemm_kernel<3><<<gC,  thr>>>(pff, Wcp, nullptr, py,      out, MM, CC, FF);
}

// round 4
// speedup vs baseline: 1.4779x; 1.4779x over previous
#include <cuda_runtime.h>
#include <math.h>

// Problem dims (fixed)
#define BB   2
#define TT   2048
#define CC   1024
#define HH   16
#define DD   64
#define HID  256
#define FF   4096
#define MM   (BB*TT)   // 4096 rows

// ---------------- scratch (device globals; no allocation allowed) ----------------
__device__ __align__(16) float g_q [MM*CC];
__device__ __align__(16) float g_k [MM*CC];
__device__ __align__(16) float g_v [MM*CC];
__device__ __align__(16) float g_h [MM*HID];
__device__ __align__(16) float g_sur[MM*HH];
__device__ __align__(16) float g_ys[MM*CC];
__device__ __align__(16) float g_y [MM*CC];
__device__ __align__(16) float g_yn[MM*CC];
__device__ __align__(16) float g_ff[MM*FF];

// ---------------- tf32 helpers ---------------------------------------------------
__device__ __forceinline__ float tf32_rna(float x) {
    float r;
    asm("cvt.rna.tf32.f32 %0, %1;" : "=f"(r) : "f"(x));
    return r;
}

__device__ __forceinline__ void mma8(float acc[4], const float a[4], const float b[2]) {
    asm volatile(
        "mma.sync.aligned.m16n8k8.row.col.f32.tf32.tf32.f32 "
        "{%0,%1,%2,%3}, {%4,%5,%6,%7}, {%8,%9}, {%0,%1,%2,%3};"
        : "+f"(acc[0]), "+f"(acc[1]), "+f"(acc[2]), "+f"(acc[3])
        : "r"(__float_as_uint(a[0])), "r"(__float_as_uint(a[1])),
          "r"(__float_as_uint(a[2])), "r"(__float_as_uint(a[3])),
          "r"(__float_as_uint(b[0])), "r"(__float_as_uint(b[1])));
}

// ---------------- tensor-core GEMM: out[M,N] = epi( A[M,K] @ W[N,K]^T ) -----------
// 3xTF32 (hi/lo split) for fp32-level accuracy.
// EPI: 0 = plain, 1 = relu(acc + bias[n]), 2 = relu(acc)^2, 3 = acc + R[m,n]
#define Bb 128
#define BN 128
#define BK 16
#define PAD 8
#define LDS_STRIDE (Bb + PAD)   // 136 floats -> bank stride 8, conflict-free frags

template<int EPI>
__global__ __launch_bounds__(256) void mma_gemm(
    const float* __restrict__ A, const float* __restrict__ W,
    const float* __restrict__ bias, const float* __restrict__ R,
    float* __restrict__ out, int M, int N, int K)
{
    __shared__ float As[BK][LDS_STRIDE];
    __shared__ float Bs[BK][LDS_STRIDE];

    const int tid  = threadIdx.x;
    const int w    = tid >> 5;
    const int lane = tid & 31;
    const int g    = lane >> 2;      // groupID 0..7
    const int tig  = lane & 3;       // thread-in-group 0..3
    const int wm   = w & 3;          // 4 warps along M (32 rows each)
    const int wn   = w >> 2;         // 2 warps along N (64 cols each)
    const int bm0  = blockIdx.y * Bb;
    const int bn0  = blockIdx.x * BN;

    float acc[2][8][4];
#pragma unroll
    for (int i = 0; i < 2; i++)
#pragma unroll
        for (int j = 0; j < 8; j++)
#pragma unroll
            for (int r = 0; r < 4; r++) acc[i][j][r] = 0.f;

    const int lr = tid >> 2;          // 0..63
    const int lk = (tid & 3) * 4;     // 0,4,8,12

    const float* aG  = A + (size_t)(bm0 + lr) * K + lk;
    const float* aG2 = aG + (size_t)64 * K;
    const float* bG  = W + (size_t)(bn0 + lr) * K + lk;
    const float* bG2 = bG + (size_t)64 * K;

    for (int k0 = 0; k0 < K; k0 += BK) {
        float4 a0 = *(const float4*)(aG  + k0);
        float4 a1 = *(const float4*)(aG2 + k0);
        float4 b0 = *(const float4*)(bG  + k0);
        float4 b1 = *(const float4*)(bG2 + k0);
        As[lk+0][lr]    = a0.x; As[lk+1][lr]    = a0.y; As[lk+2][lr]    = a0.z; As[lk+3][lr]    = a0.w;
        As[lk+0][lr+64] = a1.x; As[lk+1][lr+64] = a1.y; As[lk+2][lr+64] = a1.z; As[lk+3][lr+64] = a1.w;
        Bs[lk+0][lr]    = b0.x; Bs[lk+1][lr]    = b0.y; Bs[lk+2][lr]    = b0.z; Bs[lk+3][lr]    = b0.w;
        Bs[lk+0][lr+64] = b1.x; Bs[lk+1][lr+64] = b1.y; Bs[lk+2][lr+64] = b1.z; Bs[lk+3][lr+64] = b1.w;
        __syncthreads();

#pragma unroll
        for (int ks = 0; ks < BK; ks += 8) {
            // A fragments for the 2 m-tiles of this warp (split hi/lo)
            float ahi[2][4], alo[2][4];
#pragma unroll
            for (int i = 0; i < 2; i++) {
                const int r0 = wm * 32 + i * 16 + g;
                float f0 = As[ks + tig    ][r0];
                float f1 = As[ks + tig    ][r0 + 8];
                float f2 = As[ks + tig + 4][r0];
                float f3 = As[ks + tig + 4][r0 + 8];
                ahi[i][0] = tf32_rna(f0); alo[i][0] = tf32_rna(f0 - ahi[i][0]);
                ahi[i][1] = tf32_rna(f1); alo[i][1] = tf32_rna(f1 - ahi[i][1]);
                ahi[i][2] = tf32_rna(f2); alo[i][2] = tf32_rna(f2 - ahi[i][2]);
                ahi[i][3] = tf32_rna(f3); alo[i][3] = tf32_rna(f3 - ahi[i][3]);
            }
#pragma unroll
            for (int j = 0; j < 8; j++) {
                const int cn = wn * 64 + j * 8 + g;
                float fb0 = Bs[ks + tig    ][cn];
                float fb1 = Bs[ks + tig + 4][cn];
                float bh[2], bl[2];
                bh[0] = tf32_rna(fb0); bl[0] = tf32_rna(fb0 - bh[0]);
                bh[1] = tf32_rna(fb1); bl[1] = tf32_rna(fb1 - bh[1]);
#pragma unroll
                for (int i = 0; i < 2; i++) {
                    mma8(acc[i][j], ahi[i], bh);   // hi*hi
                    mma8(acc[i][j], ahi[i], bl);   // hi*lo
                    mma8(acc[i][j], alo[i], bh);   // lo*hi
                }
            }
        }
        __syncthreads();
    }

    // ---------------- epilogue ----------------
#pragma unroll
    for (int i = 0; i < 2; i++) {
        const int row0 = bm0 + wm * 32 + i * 16 + g;
        const int row1 = row0 + 8;
#pragma unroll
        for (int j = 0; j < 8; j++) {
            const int col = bn0 + wn * 64 + j * 8 + 2 * tig;
            float2 v01 = make_float2(acc[i][j][0], acc[i][j][1]);
            float2 v23 = make_float2(acc[i][j][2], acc[i][j][3]);
            if (EPI == 1) {
                float2 bb = *(const float2*)(bias + col);
                v01.x = fmaxf(v01.x + bb.x, 0.f); v01.y = fmaxf(v01.y + bb.y, 0.f);
                v23.x = fmaxf(v23.x + bb.x, 0.f); v23.y = fmaxf(v23.y + bb.y, 0.f);
            } else if (EPI == 2) {
                v01.x = fmaxf(v01.x, 0.f); v01.x *= v01.x;
                v01.y = fmaxf(v01.y, 0.f); v01.y *= v01.y;
                v23.x = fmaxf(v23.x, 0.f); v23.x *= v23.x;
                v23.y = fmaxf(v23.y, 0.f); v23.y *= v23.y;
            } else if (EPI == 3) {
                float2 r0v = *(const float2*)(R + (size_t)row0 * N + col);
                float2 r1v = *(const float2*)(R + (size_t)row1 * N + col);
                v01.x += r0v.x; v01.y += r0v.y;
                v23.x += r1v.x; v23.y += r1v.y;
            }
            *(float2*)(out + (size_t)row0 * N + col) = v01;
            *(float2*)(out + (size_t)row1 * N + col) = v23;
        }
    }
}

// ---------------- meta-net layer 2 + sigmoid: surprise[m,h] -----------------------
__global__ __launch_bounds__(256) void meta2_kernel(
    const float* __restrict__ hbuf, const float* __restrict__ Wm2,
    const float* __restrict__ bm2, float* __restrict__ sur)
{
    int idx = blockIdx.x * blockDim.x + threadIdx.x;   // over MM*HH
    if (idx >= MM * HH) return;
    int m = idx / HH, h = idx % HH;
    const float* hv = hbuf + (size_t)m * HID;
    const float* w  = Wm2 + (size_t)h * HID;
    float acc = bm2[h];
#pragma unroll 8
    for (int j = 0; j < HID; j++) acc += hv[j] * w[j];
    sur[idx] = 1.f / (1.f + expf(-acc));
}

// ---------------- sequential gated linear-attention scan --------------------------
// state[d][e] per (b,h); thread e owns column e. Software-pipelined loads,
// single barrier per step via double-buffered k/q staging.
__global__ __launch_bounds__(64) void scan_kernel(
    const float* __restrict__ q, const float* __restrict__ k,
    const float* __restrict__ v, const float* __restrict__ sur,
    float* __restrict__ ys)
{
    const int bh = blockIdx.x;
    const int b = bh / HH, h = bh % HH;
    const int e = threadIdx.x;

    __shared__ float sk[2][DD];
    __shared__ float sq[2][DD];

    float s[DD];
#pragma unroll
    for (int d = 0; d < DD; d++) s[d] = 0.f;

    const size_t baseBT = (size_t)b * TT * CC + (size_t)h * DD;
    const int surBase = b * TT * HH + h;

    // prefetch t=0
    float kr = k[baseBT + e];
    float qr = q[baseBT + e];
    float vr = v[baseBT + e];
    float gr = sur[surBase];

    for (int t = 0; t < TT; t++) {
        const int pb = t & 1;
        const size_t off = baseBT + (size_t)t * CC;
        sk[pb][e] = kr;
        sq[pb][e] = qr;
        const float ve = vr;
        const float gt = gr;

        // issue next step's loads before the barrier (latency hidden by compute)
        if (t + 1 < TT) {
            const size_t offn = off + CC;
            kr = k[offn + e];
            qr = q[offn + e];
            vr = v[offn + e];
            gr = sur[surBase + (t + 1) * HH];
        }
        __syncthreads();

        const float dt = 1.f - gt;
        const float c = gt * ve;
        float accum = 0.f;
#pragma unroll
        for (int d = 0; d < DD; d++) {
            s[d] = s[d] * dt + c * sk[pb][d];
            accum += sq[pb][d] * s[d];
        }
        ys[off + e] = accum;
        // no second barrier: next iteration writes the other buffer
    }
}

// ---------------- RMSNorm over last dim (C=1024) ----------------------------------
__global__ __launch_bounds__(256) void rmsnorm_kernel(
    const float* __restrict__ y, float* __restrict__ yn)
{
    const int row = blockIdx.x;
    const float* p = y + (size_t)row * CC;
    float ss = 0.f;
    for (int i = threadIdx.x; i < CC; i += 256) { float u = p[i]; ss += u * u; }

    __shared__ float red[8];
    for (int o = 16; o > 0; o >>= 1) ss += __shfl_xor_sync(0xFFFFFFFF, ss, o);
    if ((threadIdx.x & 31) == 0) red[threadIdx.x >> 5] = ss;
    __syncthreads();
    if (threadIdx.x < 8) {
        ss = red[threadIdx.x];
        for (int o = 4; o > 0; o >>= 1) ss += __shfl_xor_sync(0xFF, ss, o);
        if (threadIdx.x == 0) red[0] = ss;
    }
    __syncthreads();
    const float inv = rsqrtf(red[0] * (1.f / CC) + 1.1920928955078125e-07f);
    for (int i = threadIdx.x; i < CC; i += 256)
        yn[(size_t)row * CC + i] = p[i] * inv;
}

// ---------------- host driver -----------------------------------------------------
extern "C" void kernel_launch(void* const* d_in, const int* in_sizes, int n_in,
                              void* d_out, int out_size)
{
    const float* x     = (const float*)d_in[0];
    const float* Wq    = (const float*)d_in[1];
    const float* Wk    = (const float*)d_in[2];
    const float* Wv    = (const float*)d_in[3];
    const float* Wm1   = (const float*)d_in[4];
    const float* bm1   = (const float*)d_in[5];
    const float* Wm2   = (const float*)d_in[6];
    const float* bm2   = (const float*)d_in[7];
    const float* Wproj = (const float*)d_in[8];
    const float* Wfc   = (const float*)d_in[9];
    const float* Wcp   = (const float*)d_in[10];
    float* out = (float*)d_out;

    float *pq, *pk, *pv, *ph, *psur, *pys, *py, *pyn, *pff;
    cudaGetSymbolAddress((void**)&pq,  g_q);
    cudaGetSymbolAddress((void**)&pk,  g_k);
    cudaGetSymbolAddress((void**)&pv,  g_v);
    cudaGetSymbolAddress((void**)&ph,  g_h);
    cudaGetSymbolAddress((void**)&psur,g_sur);
    cudaGetSymbolAddress((void**)&pys, g_ys);
    cudaGetSymbolAddress((void**)&py,  g_y);
    cudaGetSymbolAddress((void**)&pyn, g_yn);
    cudaGetSymbolAddress((void**)&pff, g_ff);

    dim3 thr(256);
    dim3 gC (CC  / BN, MM / Bb);   // N=1024
    dim3 gH (HID / BN, MM / Bb);   // N=256
    dim3 gFF(FF  / BN, MM / Bb);   // N=4096

    // QKV projections
    mma_gemm<0><<<gC, thr>>>(x, Wq, nullptr, nullptr, pq, MM, CC, CC);
    mma_gemm<0><<<gC, thr>>>(x, Wk, nullptr, nullptr, pk, MM, CC, CC);
    mma_gemm<0><<<gC, thr>>>(x, Wv, nullptr, nullptr, pv, MM, CC, CC);

    // meta net: h = relu(x Wm1^T + bm1); surprise = sigmoid(h Wm2^T + bm2)
    mma_gemm<1><<<gH, thr>>>(x, Wm1, bm1, nullptr, ph, MM, HID, CC);
    meta2_kernel<<<(MM * HH + 255) / 256, thr>>>(ph, Wm2, bm2, psur);

    // gated linear-attention scan
    scan_kernel<<<BB * HH, DD>>>(pq, pk, pv, psur, pys);

    // output projection
    mma_gemm<0><<<gC, thr>>>(pys, Wproj, nullptr, nullptr, py, MM, CC, CC);

    // RMSNorm
    rmsnorm_kernel<<<MM, thr>>>(py, pyn);

    // MLP: ff = relu(yn Wfc^T)^2 ; out = y + ff Wcp^T
    mma_gemm<2><<<gFF, thr>>>(pyn, Wfc, nullptr, nullptr, pff, MM, FF, CC);
    mma_gemm<3><<<gC,  thr>>>(pff, Wcp, nullptr, py,      out, MM, CC, FF);
}

// round 7
// speedup vs baseline: 1.8342x; 1.2411x over previous
#include <cuda_runtime.h>
#include <cuda_bf16.h>
#include <stdint.h>
#include <math.h>

// Problem dims (fixed)
#define BB   2
#define TT   2048
#define CC   1024
#define HH   16
#define DD   64
#define HID  256
#define FF   4096
#define MM   (BB*TT)   // 4096 rows

// ---------------- scratch (device globals; no allocation allowed) ----------------
// fp32 intermediates
__device__ __align__(16) float g_q [MM*CC];
__device__ __align__(16) float g_k [MM*CC];
__device__ __align__(16) float g_v [MM*CC];
__device__ __align__(16) float g_h [MM*HID];
__device__ __align__(16) float g_sur[MM*HH];
__device__ __align__(16) float g_y [MM*CC];
// bf16 hi/lo split activations
__device__ __align__(16) __nv_bfloat16 g_xh [MM*CC],  g_xl [MM*CC];
__device__ __align__(16) __nv_bfloat16 g_ysh[MM*CC],  g_ysl[MM*CC];
__device__ __align__(16) __nv_bfloat16 g_ynh[MM*CC],  g_ynl[MM*CC];
__device__ __align__(16) __nv_bfloat16 g_ffh[MM*FF],  g_ffl[MM*FF];
// bf16 hi/lo split weights
__device__ __align__(16) __nv_bfloat16 g_Wqh[CC*CC],  g_Wql[CC*CC];
__device__ __align__(16) __nv_bfloat16 g_Wkh[CC*CC],  g_Wkl[CC*CC];
__device__ __align__(16) __nv_bfloat16 g_Wvh[CC*CC],  g_Wvl[CC*CC];
__device__ __align__(16) __nv_bfloat16 g_Wm1h[HID*CC], g_Wm1l[HID*CC];
__device__ __align__(16) __nv_bfloat16 g_Wph[CC*CC],  g_Wpl[CC*CC];
__device__ __align__(16) __nv_bfloat16 g_Wfh[FF*CC],  g_Wfl[FF*CC];
__device__ __align__(16) __nv_bfloat16 g_Wch[CC*FF],  g_Wcl[CC*FF];

// ---------------- helpers ---------------------------------------------------------
__device__ __forceinline__ void split2(float v, __nv_bfloat16& h, __nv_bfloat16& l) {
    h = __float2bfloat16(v);
    l = __float2bfloat16(v - __bfloat162float(h));
}

__global__ __launch_bounds__(256) void split_kernel(
    const float* __restrict__ src, __nv_bfloat16* __restrict__ hi,
    __nv_bfloat16* __restrict__ lo, int n2)   // n2 = n/2
{
    int i = blockIdx.x * 256 + threadIdx.x;
    if (i >= n2) return;
    float2 v = ((const float2*)src)[i];
    __nv_bfloat162 h, l;
    split2(v.x, h.x, l.x);
    split2(v.y, h.y, l.y);
    ((__nv_bfloat162*)hi)[i] = h;
    ((__nv_bfloat162*)lo)[i] = l;
}

__device__ __forceinline__ void cp16(void* dst, const void* src) {
    unsigned int d = (unsigned int)__cvta_generic_to_shared(dst);
    asm volatile("cp.async.cg.shared.global [%0], [%1], 16;" :: "r"(d), "l"(src));
}

__device__ __forceinline__ void mma16(float c[4], const uint32_t a[4],
                                      uint32_t b0, uint32_t b1) {
    asm volatile(
        "mma.sync.aligned.m16n8k16.row.col.f32.bf16.bf16.f32 "
        "{%0,%1,%2,%3},{%4,%5,%6,%7},{%8,%9},{%0,%1,%2,%3};"
        : "+f"(c[0]), "+f"(c[1]), "+f"(c[2]), "+f"(c[3])
        : "r"(a[0]), "r"(a[1]), "r"(a[2]), "r"(a[3]), "r"(b0), "r"(b1));
}

// ---------------- bf16x3 tensor-core GEMM: out = epi( A[M,K] @ W[N,K]^T ) ---------
// A,W pre-split into hi/lo bf16. Terms: hi*hi + hi*lo + lo*hi (lo*lo dropped).
// EPI: 0 = plain, 1 = relu(acc + bias[n]), 2 = relu(acc)^2, 3 = acc + R[m,n]
// OSPLIT: 0 -> fp32 out; 1 -> bf16 hi/lo out
#define BM   128
#define BNW  128
#define BKH  32                // k elements per stage
#define STR  40                // padded smem row stride (halfs) -> 80B, 16B aligned
#define STAGE_H (BM*STR)       // halfs per array per stage
#define SMEM_BYTES (2*4*STAGE_H*2)   // 2 stages x 4 arrays x STAGE_H halfs x 2B = 81920

template<int EPI, int OSPLIT>
__global__ __launch_bounds__(256) void bf16_gemm(
    const __nv_bfloat16* __restrict__ Ahg, const __nv_bfloat16* __restrict__ Alg,
    const __nv_bfloat16* __restrict__ Whg, const __nv_bfloat16* __restrict__ Wlg,
    const float* __restrict__ bias, const float* __restrict__ R,
    float* __restrict__ out, __nv_bfloat16* __restrict__ outh,
    __nv_bfloat16* __restrict__ outl, int M, int N, int K)
{
    extern __shared__ __nv_bfloat16 sm[];
    // stage layout: [s][Ah | Al | Bh | Bl], each STAGE_H halfs
    const int tid  = threadIdx.x;
    const int lane = tid & 31;
    const int w    = tid >> 5;
    const int g    = lane >> 2;
    const int tig  = lane & 3;
    const int wm   = w & 3;          // 4 warps along M (32 rows)
    const int wn   = w >> 2;         // 2 warps along N (64 cols)
    const int bm0  = blockIdx.y * BM;
    const int bn0  = blockIdx.x * BNW;

    float acc[2][8][4];
#pragma unroll
    for (int i = 0; i < 2; i++)
#pragma unroll
        for (int j = 0; j < 8; j++)
#pragma unroll
            for (int r = 0; r < 4; r++) acc[i][j][r] = 0.f;

    const int NK = K / BKH;

    // stage loader: 512 16B-chunks per array; 256 threads x 2
    auto load_stage = [&](int s, int k0) {
        __nv_bfloat16* base = sm + s * 4 * STAGE_H;
#pragma unroll
        for (int t = 0; t < 2; t++) {
            int tsk = tid + t * 256;
            int row = tsk >> 2;
            int ch  = (tsk & 3) * 8;
            int so  = row * STR + ch;
            cp16(base + 0 * STAGE_H + so, Ahg + (size_t)(bm0 + row) * K + k0 + ch);
            cp16(base + 1 * STAGE_H + so, Alg + (size_t)(bm0 + row) * K + k0 + ch);
            cp16(base + 2 * STAGE_H + so, Whg + (size_t)(bn0 + row) * K + k0 + ch);
            cp16(base + 3 * STAGE_H + so, Wlg + (size_t)(bn0 + row) * K + k0 + ch);
        }
    };

    load_stage(0, 0);
    asm volatile("cp.async.commit_group;");

    for (int it = 0; it < NK; it++) {
        if (it + 1 < NK) {
            load_stage((it + 1) & 1, (it + 1) * BKH);
            asm volatile("cp.async.commit_group;");
            asm volatile("cp.async.wait_group 1;");
        } else {
            asm volatile("cp.async.wait_group 0;");
        }
        __syncthreads();

        const __nv_bfloat16* base = sm + (it & 1) * 4 * STAGE_H;
        const __nv_bfloat16* pAh = base;
        const __nv_bfloat16* pAl = base + STAGE_H;
        const __nv_bfloat16* pBh = base + 2 * STAGE_H;
        const __nv_bfloat16* pBl = base + 3 * STAGE_H;

#pragma unroll
        for (int ks = 0; ks < BKH; ks += 16) {
            uint32_t ah[2][4], al[2][4];
#pragma unroll
            for (int i = 0; i < 2; i++) {
                const int r = wm * 32 + i * 16 + g;
                const __nv_bfloat16* p0 = pAh + r * STR + ks + 2 * tig;
                ah[i][0] = *(const uint32_t*)p0;
                ah[i][1] = *(const uint32_t*)(p0 + 8 * STR);
                ah[i][2] = *(const uint32_t*)(p0 + 8);
                ah[i][3] = *(const uint32_t*)(p0 + 8 * STR + 8);
                const __nv_bfloat16* p1 = pAl + r * STR + ks + 2 * tig;
                al[i][0] = *(const uint32_t*)p1;
                al[i][1] = *(const uint32_t*)(p1 + 8 * STR);
                al[i][2] = *(const uint32_t*)(p1 + 8);
                al[i][3] = *(const uint32_t*)(p1 + 8 * STR + 8);
            }
#pragma unroll
            for (int j = 0; j < 8; j++) {
                const int c = wn * 64 + j * 8 + g;
                const __nv_bfloat16* q0 = pBh + c * STR + ks + 2 * tig;
                uint32_t bh0 = *(const uint32_t*)q0;
                uint32_t bh1 = *(const uint32_t*)(q0 + 8);
                const __nv_bfloat16* q1 = pBl + c * STR + ks + 2 * tig;
                uint32_t bl0 = *(const uint32_t*)q1;
                uint32_t bl1 = *(const uint32_t*)(q1 + 8);
#pragma unroll
                for (int i = 0; i < 2; i++) {
                    mma16(acc[i][j], ah[i], bh0, bh1);   // hi*hi
                    mma16(acc[i][j], ah[i], bl0, bl1);   // hi*lo
                    mma16(acc[i][j], al[i], bh0, bh1);   // lo*hi
                }
            }
        }
        __syncthreads();
    }

    // ---------------- epilogue ----------------
#pragma unroll
    for (int i = 0; i < 2; i++) {
        const int row0 = bm0 + wm * 32 + i * 16 + g;
        const int row1 = row0 + 8;
#pragma unroll
        for (int j = 0; j < 8; j++) {
            const int col = bn0 + wn * 64 + j * 8 + 2 * tig;
            float2 v01 = make_float2(acc[i][j][0], acc[i][j][1]);
            float2 v23 = make_float2(acc[i][j][2], acc[i][j][3]);
            if (EPI == 1) {
                float2 bb = *(const float2*)(bias + col);
                v01.x = fmaxf(v01.x + bb.x, 0.f); v01.y = fmaxf(v01.y + bb.y, 0.f);
                v23.x = fmaxf(v23.x + bb.x, 0.f); v23.y = fmaxf(v23.y + bb.y, 0.f);
            } else if (EPI == 2) {
                v01.x = fmaxf(v01.x, 0.f); v01.x *= v01.x;
                v01.y = fmaxf(v01.y, 0.f); v01.y *= v01.y;
                v23.x = fmaxf(v23.x, 0.f); v23.x *= v23.x;
                v23.y = fmaxf(v23.y, 0.f); v23.y *= v23.y;
            } else if (EPI == 3) {
                float2 r0v = *(const float2*)(R + (size_t)row0 * N + col);
                float2 r1v = *(const float2*)(R + (size_t)row1 * N + col);
                v01.x += r0v.x; v01.y += r0v.y;
                v23.x += r1v.x; v23.y += r1v.y;
            }
            if (OSPLIT) {
                __nv_bfloat162 h2, l2;
                split2(v01.x, h2.x, l2.x); split2(v01.y, h2.y, l2.y);
                *(__nv_bfloat162*)(outh + (size_t)row0 * N + col) = h2;
                *(__nv_bfloat162*)(outl + (size_t)row0 * N + col) = l2;
                split2(v23.x, h2.x, l2.x); split2(v23.y, h2.y, l2.y);
                *(__nv_bfloat162*)(outh + (size_t)row1 * N + col) = h2;
                *(__nv_bfloat162*)(outl + (size_t)row1 * N + col) = l2;
            } else {
                *(float2*)(out + (size_t)row0 * N + col) = v01;
                *(float2*)(out + (size_t)row1 * N + col) = v23;
            }
        }
    }
}

// ---------------- meta-net layer 2 + sigmoid: surprise[m,h] -----------------------
__global__ __launch_bounds__(256) void meta2_kernel(
    const float* __restrict__ hbuf, const float* __restrict__ Wm2,
    const float* __restrict__ bm2, float* __restrict__ sur)
{
    int idx = blockIdx.x * blockDim.x + threadIdx.x;   // over MM*HH
    if (idx >= MM * HH) return;
    int m = idx / HH, h = idx % HH;
    const float* hv = hbuf + (size_t)m * HID;
    const float* w  = Wm2 + (size_t)h * HID;
    float acc = bm2[h];
#pragma unroll 8
    for (int j = 0; j < HID; j++) acc += hv[j] * w[j];
    sur[idx] = 1.f / (1.f + expf(-acc));
}

// ---------------- sequential gated linear-attention scan --------------------------
// Writes bf16 hi/lo directly (feeds proj GEMM).
__global__ __launch_bounds__(64) void scan_kernel(
    const float* __restrict__ q, const float* __restrict__ k,
    const float* __restrict__ v, const float* __restrict__ sur,
    __nv_bfloat16* __restrict__ ysh, __nv_bfloat16* __restrict__ ysl)
{
    const int bh = blockIdx.x;
    const int b = bh / HH, h = bh % HH;
    const int e = threadIdx.x;

    __shared__ float sk[2][DD];
    __shared__ float sq[2][DD];

    float s[DD];
#pragma unroll
    for (int d = 0; d < DD; d++) s[d] = 0.f;

    const size_t baseBT = (size_t)b * TT * CC + (size_t)h * DD;
    const int surBase = b * TT * HH + h;

    float kr = k[baseBT + e];
    float qr = q[baseBT + e];
    float vr = v[baseBT + e];
    float gr = sur[surBase];

    for (int t = 0; t < TT; t++) {
        const int pb = t & 1;
        const size_t off = baseBT + (size_t)t * CC;
        sk[pb][e] = kr;
        sq[pb][e] = qr;
        const float ve = vr;
        const float gt = gr;

        if (t + 1 < TT) {
            const size_t offn = off + CC;
            kr = k[offn + e];
            qr = q[offn + e];
            vr = v[offn + e];
            gr = sur[surBase + (t + 1) * HH];
        }
        __syncthreads();

        const float dt = 1.f - gt;
        const float c = gt * ve;
        float accum = 0.f;
#pragma unroll
        for (int d = 0; d < DD; d++) {
            s[d] = s[d] * dt + c * sk[pb][d];
            accum += sq[pb][d] * s[d];
        }
        __nv_bfloat16 hh, ll;
        split2(accum, hh, ll);
        ysh[off + e] = hh;
        ysl[off + e] = ll;
    }
}

// ---------------- RMSNorm over last dim (C=1024), emits bf16 hi/lo ----------------
__global__ __launch_bounds__(256) void rmsnorm_kernel(
    const float* __restrict__ y, __nv_bfloat16* __restrict__ ynh,
    __nv_bfloat16* __restrict__ ynl)
{
    const int row = blockIdx.x;
    const float* p = y + (size_t)row * CC;
    float ss = 0.f;
    for (int i = threadIdx.x; i < CC; i += 256) { float u = p[i]; ss += u * u; }

    __shared__ float red[8];
    for (int o = 16; o > 0; o >>= 1) ss += __shfl_xor_sync(0xFFFFFFFF, ss, o);
    if ((threadIdx.x & 31) == 0) red[threadIdx.x >> 5] = ss;
    __syncthreads();
    if (threadIdx.x < 8) {
        ss = red[threadIdx.x];
        for (int o = 4; o > 0; o >>= 1) ss += __shfl_xor_sync(0xFF, ss, o);
        if (threadIdx.x == 0) red[0] = ss;
    }
    __syncthreads();
    const float inv = rsqrtf(red[0] * (1.f / CC) + 1.1920928955078125e-07f);
    for (int i = threadIdx.x; i < CC; i += 256) {
        float u = p[i] * inv;
        __nv_bfloat16 hh, ll;
        split2(u, hh, ll);
        ynh[(size_t)row * CC + i] = hh;
        ynl[(size_t)row * CC + i] = ll;
    }
}

// ---------------- host driver -----------------------------------------------------
#define SYM(p, s) cudaGetSymbolAddress((void**)&p, s)

extern "C" void kernel_launch(void* const* d_in, const int* in_sizes, int n_in,
                              void* d_out, int out_size)
{
    const float* x     = (const float*)d_in[0];
    const float* Wq    = (const float*)d_in[1];
    const float* Wk    = (const float*)d_in[2];
    const float* Wv    = (const float*)d_in[3];
    const float* Wm1   = (const float*)d_in[4];
    const float* bm1   = (const float*)d_in[5];
    const float* Wm2   = (const float*)d_in[6];
    const float* bm2   = (const float*)d_in[7];
    const float* Wproj = (const float*)d_in[8];
    const float* Wfc   = (const float*)d_in[9];
    const float* Wcp   = (const float*)d_in[10];
    float* out = (float*)d_out;

    float *pq, *pk, *pv, *ph, *psur, *py;
    __nv_bfloat16 *pxh, *pxl, *pysh, *pysl, *pynh, *pynl, *pffh, *pffl;
    __nv_bfloat16 *pWqh, *pWql, *pWkh, *pWkl, *pWvh, *pWvl, *pWm1h, *pWm1l;
    __nv_bfloat16 *pWph, *pWpl, *pWfh, *pWfl, *pWch, *pWcl;

    SYM(pq, g_q); SYM(pk, g_k); SYM(pv, g_v); SYM(ph, g_h);
    SYM(psur, g_sur); SYM(py, g_y);
    SYM(pxh, g_xh); SYM(pxl, g_xl);
    SYM(pysh, g_ysh); SYM(pysl, g_ysl);
    SYM(pynh, g_ynh); SYM(pynl, g_ynl);
    SYM(pffh, g_ffh); SYM(pffl, g_ffl);
    SYM(pWqh, g_Wqh); SYM(pWql, g_Wql);
    SYM(pWkh, g_Wkh); SYM(pWkl, g_Wkl);
    SYM(pWvh, g_Wvh); SYM(pWvl, g_Wvl);
    SYM(pWm1h, g_Wm1h); SYM(pWm1l, g_Wm1l);
    SYM(pWph, g_Wph); SYM(pWpl, g_Wpl);
    SYM(pWfh, g_Wfh); SYM(pWfl, g_Wfl);
    SYM(pWch, g_Wch); SYM(pWcl, g_Wcl);

    // allow >48KB dynamic smem on GEMM instantiations (idempotent)
    cudaFuncSetAttribute(bf16_gemm<0,0>, cudaFuncAttributeMaxDynamicSharedMemorySize, SMEM_BYTES);
    cudaFuncSetAttribute(bf16_gemm<1,0>, cudaFuncAttributeMaxDynamicSharedMemorySize, SMEM_BYTES);
    cudaFuncSetAttribute(bf16_gemm<2,1>, cudaFuncAttributeMaxDynamicSharedMemorySize, SMEM_BYTES);
    cudaFuncSetAttribute(bf16_gemm<3,0>, cudaFuncAttributeMaxDynamicSharedMemorySize, SMEM_BYTES);

    // ---- split inputs/weights into bf16 hi/lo ----
    auto splits = [&](const float* s, __nv_bfloat16* h, __nv_bfloat16* l, int n) {
        split_kernel<<<(n / 2 + 255) / 256, 256>>>(s, h, l, n / 2);
    };
    splits(x,     pxh,  pxl,  MM * CC);
    splits(Wq,    pWqh, pWql, CC * CC);
    splits(Wk,    pWkh, pWkl, CC * CC);
    splits(Wv,    pWvh, pWvl, CC * CC);
    splits(Wm1,   pWm1h, pWm1l, HID * CC);
    splits(Wproj, pWph, pWpl, CC * CC);
    splits(Wfc,   pWfh, pWfl, FF * CC);
    splits(Wcp,   pWch, pWcl, CC * FF);

    dim3 thr(256);
    dim3 gC (CC  / BNW, MM / BM);   // N=1024
    dim3 gH (HID / BNW, MM / BM);   // N=256
    dim3 gFF(FF  / BNW, MM / BM);   // N=4096

    // QKV projections (fp32 out, feeds scan)
    bf16_gemm<0,0><<<gC, thr, SMEM_BYTES>>>(pxh, pxl, pWqh, pWql, nullptr, nullptr,
                                            pq, nullptr, nullptr, MM, CC, CC);
    bf16_gemm<0,0><<<gC, thr, SMEM_BYTES>>>(pxh, pxl, pWkh, pWkl, nullptr, nullptr,
                                            pk, nullptr, nullptr, MM, CC, CC);
    bf16_gemm<0,0><<<gC, thr, SMEM_BYTES>>>(pxh, pxl, pWvh, pWvl, nullptr, nullptr,
                                            pv, nullptr, nullptr, MM, CC, CC);

    // meta net
    bf16_gemm<1,0><<<gH, thr, SMEM_BYTES>>>(pxh, pxl, pWm1h, pWm1l, bm1, nullptr,
                                            ph, nullptr, nullptr, MM, HID, CC);
    meta2_kernel<<<(MM * HH + 255) / 256, thr>>>(ph, Wm2, bm2, psur);

    // gated linear-attention scan -> ys (bf16 hi/lo)
    scan_kernel<<<BB * HH, DD>>>(pq, pk, pv, psur, pysh, pysl);

    // output projection (fp32 y, needed for residual)
    bf16_gemm<0,0><<<gC, thr, SMEM_BYTES>>>(pysh, pysl, pWph, pWpl, nullptr, nullptr,
                                            py, nullptr, nullptr, MM, CC, CC);

    // RMSNorm -> yn (bf16 hi/lo)
    rmsnorm_kernel<<<MM, thr>>>(py, pynh, pynl);

    // MLP: ff = relu(yn Wfc^T)^2 (bf16 hi/lo) ; out = y + ff Wcp^T (fp32)
    bf16_gemm<2,1><<<gFF, thr, SMEM_BYTES>>>(pynh, pynl, pWfh, pWfl, nullptr, nullptr,
                                             nullptr, pffh, pffl, MM, FF, CC);
    bf16_gemm<3,0><<<gC, thr, SMEM_BYTES>>>(pffh, pffl, pWch, pWcl, nullptr, py,
                                            out, nullptr, nullptr, MM, CC, FF);
}

// round 8
// speedup vs baseline: 1.8874x; 1.0290x over previous
#include <cuda_runtime.h>
#include <cuda_bf16.h>
#include <stdint.h>
#include <math.h>

// Problem dims (fixed)
#define BB   2
#define TT   2048
#define CC   1024
#define HH   16
#define DD   64
#define HID  256
#define FF   4096
#define MM   (BB*TT)   // 4096 rows

// ---------------- scratch (device globals; no allocation allowed) ----------------
// fp32 intermediates
__device__ __align__(16) float g_q [MM*CC];
__device__ __align__(16) float g_k [MM*CC];
__device__ __align__(16) float g_v [MM*CC];
__device__ __align__(16) float g_h [MM*HID];
__device__ __align__(16) float g_sur[MM*HH];
__device__ __align__(16) float g_y [MM*CC];
// bf16 hi/lo split activations
__device__ __align__(16) __nv_bfloat16 g_xh [MM*CC],  g_xl [MM*CC];
__device__ __align__(16) __nv_bfloat16 g_ysh[MM*CC],  g_ysl[MM*CC];
__device__ __align__(16) __nv_bfloat16 g_ynh[MM*CC],  g_ynl[MM*CC];
__device__ __align__(16) __nv_bfloat16 g_ffh[MM*FF],  g_ffl[MM*FF];
// bf16 hi/lo split weights
__device__ __align__(16) __nv_bfloat16 g_Wqh[CC*CC],  g_Wql[CC*CC];
__device__ __align__(16) __nv_bfloat16 g_Wkh[CC*CC],  g_Wkl[CC*CC];
__device__ __align__(16) __nv_bfloat16 g_Wvh[CC*CC],  g_Wvl[CC*CC];
__device__ __align__(16) __nv_bfloat16 g_Wm1h[HID*CC], g_Wm1l[HID*CC];
__device__ __align__(16) __nv_bfloat16 g_Wph[CC*CC],  g_Wpl[CC*CC];
__device__ __align__(16) __nv_bfloat16 g_Wfh[FF*CC],  g_Wfl[FF*CC];
__device__ __align__(16) __nv_bfloat16 g_Wch[CC*FF],  g_Wcl[CC*FF];

// ---------------- helpers ---------------------------------------------------------
__device__ __forceinline__ void split2(float v, __nv_bfloat16& h, __nv_bfloat16& l) {
    h = __float2bfloat16(v);
    l = __float2bfloat16(v - __bfloat162float(h));
}

__global__ __launch_bounds__(256) void split_kernel(
    const float* __restrict__ src, __nv_bfloat16* __restrict__ hi,
    __nv_bfloat16* __restrict__ lo, int n2)   // n2 = n/2
{
    int i = blockIdx.x * 256 + threadIdx.x;
    if (i >= n2) return;
    float2 v = ((const float2*)src)[i];
    __nv_bfloat162 h, l;
    split2(v.x, h.x, l.x);
    split2(v.y, h.y, l.y);
    ((__nv_bfloat162*)hi)[i] = h;
    ((__nv_bfloat162*)lo)[i] = l;
}

__device__ __forceinline__ void cp16(void* dst, const void* src) {
    unsigned int d = (unsigned int)__cvta_generic_to_shared(dst);
    asm volatile("cp.async.cg.shared.global [%0], [%1], 16;" :: "r"(d), "l"(src));
}
__device__ __forceinline__ void cp4(void* dst, const void* src) {
    unsigned int d = (unsigned int)__cvta_generic_to_shared(dst);
    asm volatile("cp.async.ca.shared.global [%0], [%1], 4;" :: "r"(d), "l"(src));
}

__device__ __forceinline__ void mma16(float c[4], const uint32_t a[4],
                                      uint32_t b0, uint32_t b1) {
    asm volatile(
        "mma.sync.aligned.m16n8k16.row.col.f32.bf16.bf16.f32 "
        "{%0,%1,%2,%3},{%4,%5,%6,%7},{%8,%9},{%0,%1,%2,%3};"
        : "+f"(c[0]), "+f"(c[1]), "+f"(c[2]), "+f"(c[3])
        : "r"(a[0]), "r"(a[1]), "r"(a[2]), "r"(a[3]), "r"(b0), "r"(b1));
}

#define LDSM4(r, addr) \
    asm volatile("ldmatrix.sync.aligned.m8n8.x4.shared.b16 {%0,%1,%2,%3},[%4];" \
        : "=r"((r)[0]), "=r"((r)[1]), "=r"((r)[2]), "=r"((r)[3]) : "r"(addr))

// ---------------- bf16x3 tensor-core GEMM: out = epi( A[M,K] @ W[N,K]^T ) ---------
// A,W pre-split into hi/lo bf16. Terms: hi*hi + hi*lo + lo*hi (lo*lo dropped).
// EPI: 0 = plain, 1 = relu(acc + bias[n]), 2 = relu(acc)^2, 3 = acc + R[m,n]
// OSPLIT: 0 -> fp32 out; 1 -> bf16 hi/lo out
#define BM   128
#define BNW  128
#define BKH  32                // k elements per stage
#define STR  40                // padded smem row stride (halfs) -> 80B; conflict-free LDSM
#define STAGE_H (BM*STR)       // halfs per array per stage
#define SMEM_BYTES (2*4*STAGE_H*2)   // 2 stages x 4 arrays x STAGE_H halfs x 2B = 81920

template<int EPI, int OSPLIT>
__global__ __launch_bounds__(256) void bf16_gemm(
    const __nv_bfloat16* __restrict__ Ahg, const __nv_bfloat16* __restrict__ Alg,
    const __nv_bfloat16* __restrict__ Whg, const __nv_bfloat16* __restrict__ Wlg,
    const float* __restrict__ bias, const float* __restrict__ R,
    float* __restrict__ out, __nv_bfloat16* __restrict__ outh,
    __nv_bfloat16* __restrict__ outl, int M, int N, int K)
{
    extern __shared__ __nv_bfloat16 sm[];
    // stage layout: [s][Ah | Al | Bh | Bl], each STAGE_H halfs
    const int tid  = threadIdx.x;
    const int lane = tid & 31;
    const int w    = tid >> 5;
    const int g    = lane >> 2;
    const int tig  = lane & 3;
    const int wm   = w & 3;          // 4 warps along M (32 rows)
    const int wn   = w >> 2;         // 2 warps along N (64 cols)
    const int bm0  = blockIdx.y * BM;
    const int bn0  = blockIdx.x * BNW;

    const uint32_t smb = (uint32_t)__cvta_generic_to_shared(sm);
    // ldmatrix lane offset (halfs) within a 16x16 tile
    const uint32_t lofs = (uint32_t)(((lane & 7) + ((lane >> 3) & 1) * 8) * STR
                                     + (lane >> 4) * 8);

    float acc[2][8][4];
#pragma unroll
    for (int i = 0; i < 2; i++)
#pragma unroll
        for (int j = 0; j < 8; j++)
#pragma unroll
            for (int r = 0; r < 4; r++) acc[i][j][r] = 0.f;

    const int NK = K / BKH;

    // stage loader: 512 16B-chunks per array; 256 threads x 2
    auto load_stage = [&](int s, int k0) {
        __nv_bfloat16* base = sm + s * 4 * STAGE_H;
#pragma unroll
        for (int t = 0; t < 2; t++) {
            int tsk = tid + t * 256;
            int row = tsk >> 2;
            int ch  = (tsk & 3) * 8;
            int so  = row * STR + ch;
            cp16(base + 0 * STAGE_H + so, Ahg + (size_t)(bm0 + row) * K + k0 + ch);
            cp16(base + 1 * STAGE_H + so, Alg + (size_t)(bm0 + row) * K + k0 + ch);
            cp16(base + 2 * STAGE_H + so, Whg + (size_t)(bn0 + row) * K + k0 + ch);
            cp16(base + 3 * STAGE_H + so, Wlg + (size_t)(bn0 + row) * K + k0 + ch);
        }
    };

    load_stage(0, 0);
    asm volatile("cp.async.commit_group;");

    for (int it = 0; it < NK; it++) {
        if (it + 1 < NK) {
            load_stage((it + 1) & 1, (it + 1) * BKH);
            asm volatile("cp.async.commit_group;");
            asm volatile("cp.async.wait_group 1;");
        } else {
            asm volatile("cp.async.wait_group 0;");
        }
        __syncthreads();

        const uint32_t stageB = smb + (uint32_t)((it & 1) * 4 * STAGE_H) * 2;

#pragma unroll
        for (int ks = 0; ks < BKH; ks += 16) {
            uint32_t ah[2][4], al[2][4];
#pragma unroll
            for (int i = 0; i < 2; i++) {
                uint32_t ta = stageB + 2u * ((uint32_t)((wm * 32 + i * 16) * STR + ks) + lofs);
                LDSM4(ah[i], ta);
                LDSM4(al[i], ta + 2u * STAGE_H);
            }
            uint32_t bh[4][4], bl[4][4];
#pragma unroll
            for (int jp = 0; jp < 4; jp++) {
                uint32_t tb = stageB + 2u * ((uint32_t)(2 * STAGE_H
                              + (wn * 64 + jp * 16) * STR + ks) + lofs);
                LDSM4(bh[jp], tb);
                LDSM4(bl[jp], tb + 2u * STAGE_H);
            }
#pragma unroll
            for (int jp = 0; jp < 4; jp++) {
#pragma unroll
                for (int sub = 0; sub < 2; sub++) {
                    const int j = jp * 2 + sub;
                    uint32_t bh0 = bh[jp][sub], bh1 = bh[jp][sub + 2];
                    uint32_t bl0 = bl[jp][sub], bl1 = bl[jp][sub + 2];
#pragma unroll
                    for (int i = 0; i < 2; i++) {
                        mma16(acc[i][j], ah[i], bh0, bh1);   // hi*hi
                        mma16(acc[i][j], ah[i], bl0, bl1);   // hi*lo
                        mma16(acc[i][j], al[i], bh0, bh1);   // lo*hi
                    }
                }
            }
        }
        __syncthreads();
    }

    // ---------------- epilogue ----------------
#pragma unroll
    for (int i = 0; i < 2; i++) {
        const int row0 = bm0 + wm * 32 + i * 16 + g;
        const int row1 = row0 + 8;
#pragma unroll
        for (int j = 0; j < 8; j++) {
            const int col = bn0 + wn * 64 + j * 8 + 2 * tig;
            float2 v01 = make_float2(acc[i][j][0], acc[i][j][1]);
            float2 v23 = make_float2(acc[i][j][2], acc[i][j][3]);
            if (EPI == 1) {
                float2 bb = *(const float2*)(bias + col);
                v01.x = fmaxf(v01.x + bb.x, 0.f); v01.y = fmaxf(v01.y + bb.y, 0.f);
                v23.x = fmaxf(v23.x + bb.x, 0.f); v23.y = fmaxf(v23.y + bb.y, 0.f);
            } else if (EPI == 2) {
                v01.x = fmaxf(v01.x, 0.f); v01.x *= v01.x;
                v01.y = fmaxf(v01.y, 0.f); v01.y *= v01.y;
                v23.x = fmaxf(v23.x, 0.f); v23.x *= v23.x;
                v23.y = fmaxf(v23.y, 0.f); v23.y *= v23.y;
            } else if (EPI == 3) {
                float2 r0v = *(const float2*)(R + (size_t)row0 * N + col);
                float2 r1v = *(const float2*)(R + (size_t)row1 * N + col);
                v01.x += r0v.x; v01.y += r0v.y;
                v23.x += r1v.x; v23.y += r1v.y;
            }
            if (OSPLIT) {
                __nv_bfloat162 h2, l2;
                split2(v01.x, h2.x, l2.x); split2(v01.y, h2.y, l2.y);
                *(__nv_bfloat162*)(outh + (size_t)row0 * N + col) = h2;
                *(__nv_bfloat162*)(outl + (size_t)row0 * N + col) = l2;
                split2(v23.x, h2.x, l2.x); split2(v23.y, h2.y, l2.y);
                *(__nv_bfloat162*)(outh + (size_t)row1 * N + col) = h2;
                *(__nv_bfloat162*)(outl + (size_t)row1 * N + col) = l2;
            } else {
                *(float2*)(out + (size_t)row0 * N + col) = v01;
                *(float2*)(out + (size_t)row1 * N + col) = v23;
            }
        }
    }
}

// ---------------- meta-net layer 2 + sigmoid: surprise[m,h] -----------------------
__global__ __launch_bounds__(256) void meta2_kernel(
    const float* __restrict__ hbuf, const float* __restrict__ Wm2,
    const float* __restrict__ bm2, float* __restrict__ sur)
{
    int idx = blockIdx.x * blockDim.x + threadIdx.x;   // over MM*HH
    if (idx >= MM * HH) return;
    int m = idx / HH, h = idx % HH;
    const float* hv = hbuf + (size_t)m * HID;
    const float* w  = Wm2 + (size_t)h * HID;
    float acc = bm2[h];
#pragma unroll 8
    for (int j = 0; j < HID; j++) acc += hv[j] * w[j];
    sur[idx] = 1.f / (1.f + expf(-acc));
}

// ---------------- sequential gated linear-attention scan --------------------------
// Grid: BB*HH*2 blocks (each handles 32 of the 64 v/e columns), 256 threads.
// Thread (e,dg) owns 8 state rows d = dg*8..dg*8+7 for column e.
// k/q/v/g staged through a 4-stage x 4-timestep cp.async ring.
#define NSTG 4
#define SUBT 4
#define SSTEP 164   // floats per timestep: k[64] q[64] v[32] g[1] pad[3]

__global__ __launch_bounds__(256) void scan_kernel(
    const float* __restrict__ q, const float* __restrict__ k,
    const float* __restrict__ v, const float* __restrict__ sur,
    __nv_bfloat16* __restrict__ ysh, __nv_bfloat16* __restrict__ ysl)
{
    __shared__ float ring[NSTG][SUBT][SSTEP];

    const int bid = blockIdx.x;
    const int b  = bid / (HH * 2);
    const int rem = bid % (HH * 2);
    const int h  = rem >> 1;
    const int eh = rem & 1;          // which 32-column half
    const int tid = threadIdx.x;
    const int dg  = tid & 7;         // d-group: 8 rows each
    const int el  = tid >> 3;        // 0..31
    const int e   = eh * 32 + el;
    const int d0  = dg * 8;

    const size_t baseBT = (size_t)b * TT * CC + (size_t)h * DD;
    const size_t surBase = (size_t)b * TT * HH + h;

    float s[8];
#pragma unroll
    for (int i = 0; i < 8; i++) s[i] = 0.f;

    // producer: 160 16B chunks + 4 4B g's per stage
    auto fill = [&](int stg, int t0) {
        if (tid < 160) {
            int st = tid / 40, c = tid % 40;
            int t = t0 + st;
            if (t < TT) {
                size_t off = baseBT + (size_t)t * CC;
                if (c < 16)
                    cp16(&ring[stg][st][c * 4], k + off + c * 4);
                else if (c < 32)
                    cp16(&ring[stg][st][64 + (c - 16) * 4], q + off + (c - 16) * 4);
                else
                    cp16(&ring[stg][st][128 + (c - 32) * 4], v + off + eh * 32 + (c - 32) * 4);
            }
        } else if (tid < 164) {
            int st = tid - 160;
            int t = t0 + st;
            if (t < TT)
                cp4(&ring[stg][st][160], sur + surBase + (size_t)t * HH);
        }
    };

#pragma unroll
    for (int i = 0; i < NSTG; i++) {
        fill(i, i * SUBT);
        asm volatile("cp.async.commit_group;");
    }

    const int NB = TT / SUBT;   // 512
    for (int ib = 0; ib < NB; ib++) {
        asm volatile("cp.async.wait_group %0;" :: "n"(NSTG - 1));
        __syncthreads();
        const int stg = ib & (NSTG - 1);

#pragma unroll
        for (int st = 0; st < SUBT; st++) {
            const float* row = ring[stg][st];
            const float gt = row[160];
            const float ve = row[128 + el];
            const float dt = 1.f - gt;
            const float c  = gt * ve;
            float accum = 0.f;
#pragma unroll
            for (int i = 0; i < 8; i++) {
                float kv = row[d0 + i];
                float qv = row[64 + d0 + i];
                s[i] = s[i] * dt + c * kv;
                accum = fmaf(qv, s[i], accum);
            }
            accum += __shfl_xor_sync(0xFFFFFFFF, accum, 1);
            accum += __shfl_xor_sync(0xFFFFFFFF, accum, 2);
            accum += __shfl_xor_sync(0xFFFFFFFF, accum, 4);
            if (dg == 0) {
                const int t = ib * SUBT + st;
                const size_t off = baseBT + (size_t)t * CC + e;
                __nv_bfloat16 hh, ll;
                split2(accum, hh, ll);
                ysh[off] = hh;
                ysl[off] = ll;
            }
        }
        __syncthreads();
        fill(stg, (ib + NSTG) * SUBT);
        asm volatile("cp.async.commit_group;");
    }
}

// ---------------- RMSNorm over last dim (C=1024), emits bf16 hi/lo ----------------
__global__ __launch_bounds__(256) void rmsnorm_kernel(
    const float* __restrict__ y, __nv_bfloat16* __restrict__ ynh,
    __nv_bfloat16* __restrict__ ynl)
{
    const int row = blockIdx.x;
    const float* p = y + (size_t)row * CC;
    float ss = 0.f;
    for (int i = threadIdx.x; i < CC; i += 256) { float u = p[i]; ss += u * u; }

    __shared__ float red[8];
    for (int o = 16; o > 0; o >>= 1) ss += __shfl_xor_sync(0xFFFFFFFF, ss, o);
    if ((threadIdx.x & 31) == 0) red[threadIdx.x >> 5] = ss;
    __syncthreads();
    if (threadIdx.x < 8) {
        ss = red[threadIdx.x];
        for (int o = 4; o > 0; o >>= 1) ss += __shfl_xor_sync(0xFF, ss, o);
        if (threadIdx.x == 0) red[0] = ss;
    }
    __syncthreads();
    const float inv = rsqrtf(red[0] * (1.f / CC) + 1.1920928955078125e-07f);
    for (int i = threadIdx.x; i < CC; i += 256) {
        float u = p[i] * inv;
        __nv_bfloat16 hh, ll;
        split2(u, hh, ll);
        ynh[(size_t)row * CC + i] = hh;
        ynl[(size_t)row * CC + i] = ll;
    }
}

// ---------------- host driver -----------------------------------------------------
#define SYM(p, s) cudaGetSymbolAddress((void**)&p, s)

extern "C" void kernel_launch(void* const* d_in, const int* in_sizes, int n_in,
                              void* d_out, int out_size)
{
    const float* x     = (const float*)d_in[0];
    const float* Wq    = (const float*)d_in[1];
    const float* Wk    = (const float*)d_in[2];
    const float* Wv    = (const float*)d_in[3];
    const float* Wm1   = (const float*)d_in[4];
    const float* bm1   = (const float*)d_in[5];
    const float* Wm2   = (const float*)d_in[6];
    const float* bm2   = (const float*)d_in[7];
    const float* Wproj = (const float*)d_in[8];
    const float* Wfc   = (const float*)d_in[9];
    const float* Wcp   = (const float*)d_in[10];
    float* out = (float*)d_out;

    float *pq, *pk, *pv, *ph, *psur, *py;
    __nv_bfloat16 *pxh, *pxl, *pysh, *pysl, *pynh, *pynl, *pffh, *pffl;
    __nv_bfloat16 *pWqh, *pWql, *pWkh, *pWkl, *pWvh, *pWvl, *pWm1h, *pWm1l;
    __nv_bfloat16 *pWph, *pWpl, *pWfh, *pWfl, *pWch, *pWcl;

    SYM(pq, g_q); SYM(pk, g_k); SYM(pv, g_v); SYM(ph, g_h);
    SYM(psur, g_sur); SYM(py, g_y);
    SYM(pxh, g_xh); SYM(pxl, g_xl);
    SYM(pysh, g_ysh); SYM(pysl, g_ysl);
    SYM(pynh, g_ynh); SYM(pynl, g_ynl);
    SYM(pffh, g_ffh); SYM(pffl, g_ffl);
    SYM(pWqh, g_Wqh); SYM(pWql, g_Wql);
    SYM(pWkh, g_Wkh); SYM(pWkl, g_Wkl);
    SYM(pWvh, g_Wvh); SYM(pWvl, g_Wvl);
    SYM(pWm1h, g_Wm1h); SYM(pWm1l, g_Wm1l);
    SYM(pWph, g_Wph); SYM(pWpl, g_Wpl);
    SYM(pWfh, g_Wfh); SYM(pWfl, g_Wfl);
    SYM(pWch, g_Wch); SYM(pWcl, g_Wcl);

    // allow >48KB dynamic smem on GEMM instantiations (idempotent)
    cudaFuncSetAttribute(bf16_gemm<0,0>, cudaFuncAttributeMaxDynamicSharedMemorySize, SMEM_BYTES);
    cudaFuncSetAttribute(bf16_gemm<1,0>, cudaFuncAttributeMaxDynamicSharedMemorySize, SMEM_BYTES);
    cudaFuncSetAttribute(bf16_gemm<2,1>, cudaFuncAttributeMaxDynamicSharedMemorySize, SMEM_BYTES);
    cudaFuncSetAttribute(bf16_gemm<3,0>, cudaFuncAttributeMaxDynamicSharedMemorySize, SMEM_BYTES);

    // ---- split inputs/weights into bf16 hi/lo ----
    auto splits = [&](const float* s, __nv_bfloat16* h, __nv_bfloat16* l, int n) {
        split_kernel<<<(n / 2 + 255) / 256, 256>>>(s, h, l, n / 2);
    };
    splits(x,     pxh,  pxl,  MM * CC);
    splits(Wq,    pWqh, pWql, CC * CC);
    splits(Wk,    pWkh, pWkl, CC * CC);
    splits(Wv,    pWvh, pWvl, CC * CC);
    splits(Wm1,   pWm1h, pWm1l, HID * CC);
    splits(Wproj, pWph, pWpl, CC * CC);
    splits(Wfc,   pWfh, pWfl, FF * CC);
    splits(Wcp,   pWch, pWcl, CC * FF);

    dim3 thr(256);
    dim3 gC (CC  / BNW, MM / BM);   // N=1024
    dim3 gH (HID / BNW, MM / BM);   // N=256
    dim3 gFF(FF  / BNW, MM / BM);   // N=4096

    // QKV projections (fp32 out, feeds scan)
    bf16_gemm<0,0><<<gC, thr, SMEM_BYTES>>>(pxh, pxl, pWqh, pWql, nullptr, nullptr,
                                            pq, nullptr, nullptr, MM, CC, CC);
    bf16_gemm<0,0><<<gC, thr, SMEM_BYTES>>>(pxh, pxl, pWkh, pWkl, nullptr, nullptr,
                                            pk, nullptr, nullptr, MM, CC, CC);
    bf16_gemm<0,0><<<gC, thr, SMEM_BYTES>>>(pxh, pxl, pWvh, pWvl, nullptr, nullptr,
                                            pv, nullptr, nullptr, MM, CC, CC);

    // meta net
    bf16_gemm<1,0><<<gH, thr, SMEM_BYTES>>>(pxh, pxl, pWm1h, pWm1l, bm1, nullptr,
                                            ph, nullptr, nullptr, MM, HID, CC);
    meta2_kernel<<<(MM * HH + 255) / 256, thr>>>(ph, Wm2, bm2, psur);

    // gated linear-attention scan -> ys (bf16 hi/lo)
    scan_kernel<<<BB * HH * 2, 256>>>(pq, pk, pv, psur, pysh, pysl);

    // output projection (fp32 y, needed for residual)
    bf16_gemm<0,0><<<gC, thr, SMEM_BYTES>>>(pysh, pysl, pWph, pWpl, nullptr, nullptr,
                                            py, nullptr, nullptr, MM, CC, CC);

    // RMSNorm -> yn (bf16 hi/lo)
    rmsnorm_kernel<<<MM, thr>>>(py, pynh, pynl);

    // MLP: ff = relu(yn Wfc^T)^2 (bf16 hi/lo) ; out = y + ff Wcp^T (fp32)
    bf16_gemm<2,1><<<gFF, thr, SMEM_BYTES>>>(pynh, pynl, pWfh, pWfl, nullptr, nullptr,
                                             nullptr, pffh, pffl, MM, FF, CC);
    bf16_gemm<3,0><<<gC, thr, SMEM_BYTES>>>(pffh, pffl, pWch, pWcl, nullptr, py,
                                            out, nullptr, nullptr, MM, CC, FF);
}

// round 9
// speedup vs baseline: 3.0382x; 1.6097x over previous
#include <cuda_runtime.h>
#include <cuda_bf16.h>
#include <stdint.h>
#include <math.h>

// Problem dims (fixed)
#define BB   2
#define TT   2048
#define CC   1024
#define HH   16
#define DD   64
#define HID  256
#define FF   4096
#define MM   (BB*TT)   // 4096 rows
#define C3   (3*CC)    // fused qkv width

// ---------------- scratch (device globals; no allocation allowed) ----------------
__device__ __align__(16) float g_qkv[MM*C3];     // fused q|k|v fp32
__device__ __align__(16) float g_h [MM*HID];
__device__ __align__(16) float g_sur[MM*HH];
__device__ __align__(16) float g_y [MM*CC];
// bf16 hi/lo split activations
__device__ __align__(16) __nv_bfloat16 g_xh [MM*CC],  g_xl [MM*CC];
__device__ __align__(16) __nv_bfloat16 g_ysh[MM*CC],  g_ysl[MM*CC];
__device__ __align__(16) __nv_bfloat16 g_ynh[MM*CC],  g_ynl[MM*CC];
__device__ __align__(16) __nv_bfloat16 g_ffh[MM*FF],  g_ffl[MM*FF];
// bf16 hi/lo split weights (qkv concatenated [3C, C])
__device__ __align__(16) __nv_bfloat16 g_Wqkvh[C3*CC], g_Wqkvl[C3*CC];
__device__ __align__(16) __nv_bfloat16 g_Wm1h[HID*CC], g_Wm1l[HID*CC];
__device__ __align__(16) __nv_bfloat16 g_Wph[CC*CC],  g_Wpl[CC*CC];
__device__ __align__(16) __nv_bfloat16 g_Wfh[FF*CC],  g_Wfl[FF*CC];
__device__ __align__(16) __nv_bfloat16 g_Wch[CC*FF],  g_Wcl[CC*FF];

// ---------------- helpers ---------------------------------------------------------
__device__ __forceinline__ void split2(float v, __nv_bfloat16& h, __nv_bfloat16& l) {
    h = __float2bfloat16(v);
    l = __float2bfloat16(v - __bfloat162float(h));
}

__global__ __launch_bounds__(256) void split_kernel(
    const float* __restrict__ src, __nv_bfloat16* __restrict__ hi,
    __nv_bfloat16* __restrict__ lo, int n2)   // n2 = n/2
{
    int i = blockIdx.x * 256 + threadIdx.x;
    if (i >= n2) return;
    float2 v = ((const float2*)src)[i];
    __nv_bfloat162 h, l;
    split2(v.x, h.x, l.x);
    split2(v.y, h.y, l.y);
    ((__nv_bfloat162*)hi)[i] = h;
    ((__nv_bfloat162*)lo)[i] = l;
}

__device__ __forceinline__ void cp16(void* dst, const void* src) {
    unsigned int d = (unsigned int)__cvta_generic_to_shared(dst);
    asm volatile("cp.async.cg.shared.global [%0], [%1], 16;" :: "r"(d), "l"(src));
}
__device__ __forceinline__ void cp4(void* dst, const void* src) {
    unsigned int d = (unsigned int)__cvta_generic_to_shared(dst);
    asm volatile("cp.async.ca.shared.global [%0], [%1], 4;" :: "r"(d), "l"(src));
}

__device__ __forceinline__ void mma16(float c[4], const uint32_t a[4],
                                      uint32_t b0, uint32_t b1) {
    asm volatile(
        "mma.sync.aligned.m16n8k16.row.col.f32.bf16.bf16.f32 "
        "{%0,%1,%2,%3},{%4,%5,%6,%7},{%8,%9},{%0,%1,%2,%3};"
        : "+f"(c[0]), "+f"(c[1]), "+f"(c[2]), "+f"(c[3])
        : "r"(a[0]), "r"(a[1]), "r"(a[2]), "r"(a[3]), "r"(b0), "r"(b1));
}

#define LDSM4(r, addr) \
    asm volatile("ldmatrix.sync.aligned.m8n8.x4.shared.b16 {%0,%1,%2,%3},[%4];" \
        : "=r"((r)[0]), "=r"((r)[1]), "=r"((r)[2]), "=r"((r)[3]) : "r"(addr))

// ---------------- bf16x3 tensor-core GEMM: out = epi( A[M,K] @ W[N,K]^T ) ---------
// EPI: 0 = plain, 1 = relu(acc + bias[n]), 2 = relu(acc)^2, 3 = acc + R[m,n]
// OSPLIT: 0 -> fp32 out; 1 -> bf16 hi/lo out
#define BM   128
#define BNW  128
#define BKH  32                // k elements per stage
#define STR  40                // padded smem row stride (halfs) -> 80B; conflict-free LDSM
#define STAGE_H (BM*STR)       // halfs per array per stage
#define SMEM_BYTES (2*4*STAGE_H*2)   // 81920 B

template<int EPI, int OSPLIT>
__global__ __launch_bounds__(256, 2) void bf16_gemm(
    const __nv_bfloat16* __restrict__ Ahg, const __nv_bfloat16* __restrict__ Alg,
    const __nv_bfloat16* __restrict__ Whg, const __nv_bfloat16* __restrict__ Wlg,
    const float* __restrict__ bias, const float* __restrict__ R,
    float* __restrict__ out, __nv_bfloat16* __restrict__ outh,
    __nv_bfloat16* __restrict__ outl, int M, int N, int K)
{
    extern __shared__ __nv_bfloat16 sm[];
    const int tid  = threadIdx.x;
    const int lane = tid & 31;
    const int w    = tid >> 5;
    const int g    = lane >> 2;
    const int tig  = lane & 3;
    const int wm   = w & 3;          // 4 warps along M (32 rows)
    const int wn   = w >> 2;         // 2 warps along N (64 cols)
    const int bm0  = blockIdx.y * BM;
    const int bn0  = blockIdx.x * BNW;

    const uint32_t smb = (uint32_t)__cvta_generic_to_shared(sm);
    const uint32_t lofs = (uint32_t)(((lane & 7) + ((lane >> 3) & 1) * 8) * STR
                                     + (lane >> 4) * 8);

    float acc[2][8][4];
#pragma unroll
    for (int i = 0; i < 2; i++)
#pragma unroll
        for (int j = 0; j < 8; j++)
#pragma unroll
            for (int r = 0; r < 4; r++) acc[i][j][r] = 0.f;

    const int NK = K / BKH;

    auto load_stage = [&](int s, int k0) {
        __nv_bfloat16* base = sm + s * 4 * STAGE_H;
#pragma unroll
        for (int t = 0; t < 2; t++) {
            int tsk = tid + t * 256;
            int row = tsk >> 2;
            int ch  = (tsk & 3) * 8;
            int so  = row * STR + ch;
            cp16(base + 0 * STAGE_H + so, Ahg + (size_t)(bm0 + row) * K + k0 + ch);
            cp16(base + 1 * STAGE_H + so, Alg + (size_t)(bm0 + row) * K + k0 + ch);
            cp16(base + 2 * STAGE_H + so, Whg + (size_t)(bn0 + row) * K + k0 + ch);
            cp16(base + 3 * STAGE_H + so, Wlg + (size_t)(bn0 + row) * K + k0 + ch);
        }
    };

    load_stage(0, 0);
    asm volatile("cp.async.commit_group;");

    for (int it = 0; it < NK; it++) {
        if (it + 1 < NK) {
            load_stage((it + 1) & 1, (it + 1) * BKH);
            asm volatile("cp.async.commit_group;");
            asm volatile("cp.async.wait_group 1;");
        } else {
            asm volatile("cp.async.wait_group 0;");
        }
        __syncthreads();

        const uint32_t stageB = smb + (uint32_t)((it & 1) * 4 * STAGE_H) * 2;

#pragma unroll
        for (int ks = 0; ks < BKH; ks += 16) {
            uint32_t ah[2][4], al[2][4];
#pragma unroll
            for (int i = 0; i < 2; i++) {
                uint32_t ta = stageB + 2u * ((uint32_t)((wm * 32 + i * 16) * STR + ks) + lofs);
                LDSM4(ah[i], ta);
                LDSM4(al[i], ta + 2u * STAGE_H);
            }
            // B fragments loaded per-jp to keep live registers low (2 CTAs/SM)
#pragma unroll
            for (int jp = 0; jp < 4; jp++) {
                uint32_t bh[4], bl[4];
                uint32_t tb = stageB + 2u * ((uint32_t)(2 * STAGE_H
                              + (wn * 64 + jp * 16) * STR + ks) + lofs);
                LDSM4(bh, tb);
                LDSM4(bl, tb + 2u * STAGE_H);
#pragma unroll
                for (int sub = 0; sub < 2; sub++) {
                    const int j = jp * 2 + sub;
                    uint32_t bh0 = bh[sub], bh1 = bh[sub + 2];
                    uint32_t bl0 = bl[sub], bl1 = bl[sub + 2];
#pragma unroll
                    for (int i = 0; i < 2; i++) {
                        mma16(acc[i][j], ah[i], bh0, bh1);   // hi*hi
                        mma16(acc[i][j], ah[i], bl0, bl1);   // hi*lo
                        mma16(acc[i][j], al[i], bh0, bh1);   // lo*hi
                    }
                }
            }
        }
        __syncthreads();
    }

    // ---------------- epilogue ----------------
#pragma unroll
    for (int i = 0; i < 2; i++) {
        const int row0 = bm0 + wm * 32 + i * 16 + g;
        const int row1 = row0 + 8;
#pragma unroll
        for (int j = 0; j < 8; j++) {
            const int col = bn0 + wn * 64 + j * 8 + 2 * tig;
            float2 v01 = make_float2(acc[i][j][0], acc[i][j][1]);
            float2 v23 = make_float2(acc[i][j][2], acc[i][j][3]);
            if (EPI == 1) {
                float2 bb = *(const float2*)(bias + col);
                v01.x = fmaxf(v01.x + bb.x, 0.f); v01.y = fmaxf(v01.y + bb.y, 0.f);
                v23.x = fmaxf(v23.x + bb.x, 0.f); v23.y = fmaxf(v23.y + bb.y, 0.f);
            } else if (EPI == 2) {
                v01.x = fmaxf(v01.x, 0.f); v01.x *= v01.x;
                v01.y = fmaxf(v01.y, 0.f); v01.y *= v01.y;
                v23.x = fmaxf(v23.x, 0.f); v23.x *= v23.x;
                v23.y = fmaxf(v23.y, 0.f); v23.y *= v23.y;
            } else if (EPI == 3) {
                float2 r0v = *(const float2*)(R + (size_t)row0 * N + col);
                float2 r1v = *(const float2*)(R + (size_t)row1 * N + col);
                v01.x += r0v.x; v01.y += r0v.y;
                v23.x += r1v.x; v23.y += r1v.y;
            }
            if (OSPLIT) {
                __nv_bfloat162 h2, l2;
                split2(v01.x, h2.x, l2.x); split2(v01.y, h2.y, l2.y);
                *(__nv_bfloat162*)(outh + (size_t)row0 * N + col) = h2;
                *(__nv_bfloat162*)(outl + (size_t)row0 * N + col) = l2;
                split2(v23.x, h2.x, l2.x); split2(v23.y, h2.y, l2.y);
                *(__nv_bfloat162*)(outh + (size_t)row1 * N + col) = h2;
                *(__nv_bfloat162*)(outl + (size_t)row1 * N + col) = l2;
            } else {
                *(float2*)(out + (size_t)row0 * N + col) = v01;
                *(float2*)(out + (size_t)row1 * N + col) = v23;
            }
        }
    }
}

// ---------------- meta-net layer 2 + sigmoid: surprise[m,h] -----------------------
__global__ __launch_bounds__(256) void meta2_kernel(
    const float* __restrict__ hbuf, const float* __restrict__ Wm2,
    const float* __restrict__ bm2, float* __restrict__ sur)
{
    int idx = blockIdx.x * blockDim.x + threadIdx.x;   // over MM*HH
    if (idx >= MM * HH) return;
    int m = idx / HH, h = idx % HH;
    const float* hv = hbuf + (size_t)m * HID;
    const float* w  = Wm2 + (size_t)h * HID;
    float acc = bm2[h];
#pragma unroll 8
    for (int j = 0; j < HID; j++) acc += hv[j] * w[j];
    sur[idx] = 1.f / (1.f + expf(-acc));
}

// ---------------- sequential gated linear-attention scan --------------------------
// Inputs read from fused qkv buffer (row stride C3); output ys (stride CC) bf16 hi/lo.
#define NSTG 4
#define SUBT 4
#define SSTEP 164   // floats per timestep: k[64] q[64] v[32] g[1] pad[3]

__global__ __launch_bounds__(256) void scan_kernel(
    const float* __restrict__ qkv, const float* __restrict__ sur,
    __nv_bfloat16* __restrict__ ysh, __nv_bfloat16* __restrict__ ysl)
{
    __shared__ float ring[NSTG][SUBT][SSTEP];

    const int bid = blockIdx.x;
    const int b  = bid / (HH * 2);
    const int rem = bid % (HH * 2);
    const int h  = rem >> 1;
    const int eh = rem & 1;          // which 32-column half
    const int tid = threadIdx.x;
    const int dg  = tid & 7;         // d-group: 8 rows each
    const int el  = tid >> 3;        // 0..31
    const int e   = eh * 32 + el;
    const int d0  = dg * 8;

    const size_t baseIn  = (size_t)b * TT * C3 + (size_t)h * DD;  // q section
    const size_t baseOut = (size_t)b * TT * CC + (size_t)h * DD;
    const size_t surBase = (size_t)b * TT * HH + h;

    float s[8];
#pragma unroll
    for (int i = 0; i < 8; i++) s[i] = 0.f;

    // producer: 160 16B chunks + 4 4B g's per stage
    auto fill = [&](int stg, int t0) {
        if (tid < 160) {
            int st = tid / 40, c = tid % 40;
            int t = t0 + st;
            if (t < TT) {
                size_t off = baseIn + (size_t)t * C3;
                if (c < 16)        // k section (+CC)
                    cp16(&ring[stg][st][c * 4], qkv + off + CC + c * 4);
                else if (c < 32)   // q section (+0)
                    cp16(&ring[stg][st][64 + (c - 16) * 4], qkv + off + (c - 16) * 4);
                else               // v section (+2CC), this block's half
                    cp16(&ring[stg][st][128 + (c - 32) * 4],
                         qkv + off + 2 * CC + eh * 32 + (c - 32) * 4);
            }
        } else if (tid < 164) {
            int st = tid - 160;
            int t = t0 + st;
            if (t < TT)
                cp4(&ring[stg][st][160], sur + surBase + (size_t)t * HH);
        }
    };

#pragma unroll
    for (int i = 0; i < NSTG; i++) {
        fill(i, i * SUBT);
        asm volatile("cp.async.commit_group;");
    }

    const int NB = TT / SUBT;   // 512
    for (int ib = 0; ib < NB; ib++) {
        asm volatile("cp.async.wait_group %0;" :: "n"(NSTG - 1));
        __syncthreads();
        const int stg = ib & (NSTG - 1);

#pragma unroll
        for (int st = 0; st < SUBT; st++) {
            const float* row = ring[stg][st];
            const float gt = row[160];
            const float ve = row[128 + el];
            const float dt = 1.f - gt;
            const float c  = gt * ve;
            float accum = 0.f;
#pragma unroll
            for (int i = 0; i < 8; i++) {
                float kv = row[d0 + i];
                float qv = row[64 + d0 + i];
                s[i] = s[i] * dt + c * kv;
                accum = fmaf(qv, s[i], accum);
            }
            accum += __shfl_xor_sync(0xFFFFFFFF, accum, 1);
            accum += __shfl_xor_sync(0xFFFFFFFF, accum, 2);
            accum += __shfl_xor_sync(0xFFFFFFFF, accum, 4);
            if (dg == 0) {
                const int t = ib * SUBT + st;
                const size_t off = baseOut + (size_t)t * CC + e;
                __nv_bfloat16 hh, ll;
                split2(accum, hh, ll);
                ysh[off] = hh;
                ysl[off] = ll;
            }
        }
        __syncthreads();
        fill(stg, (ib + NSTG) * SUBT);
        asm volatile("cp.async.commit_group;");
    }
}

// ---------------- RMSNorm over last dim (C=1024), emits bf16 hi/lo ----------------
__global__ __launch_bounds__(256) void rmsnorm_kernel(
    const float* __restrict__ y, __nv_bfloat16* __restrict__ ynh,
    __nv_bfloat16* __restrict__ ynl)
{
    const int row = blockIdx.x;
    const float* p = y + (size_t)row * CC;
    float ss = 0.f;
    for (int i = threadIdx.x; i < CC; i += 256) { float u = p[i]; ss += u * u; }

    __shared__ float red[8];
    for (int o = 16; o > 0; o >>= 1) ss += __shfl_xor_sync(0xFFFFFFFF, ss, o);
    if ((threadIdx.x & 31) == 0) red[threadIdx.x >> 5] = ss;
    __syncthreads();
    if (threadIdx.x < 8) {
        ss = red[threadIdx.x];
        for (int o = 4; o > 0; o >>= 1) ss += __shfl_xor_sync(0xFF, ss, o);
        if (threadIdx.x == 0) red[0] = ss;
    }
    __syncthreads();
    const float inv = rsqrtf(red[0] * (1.f / CC) + 1.1920928955078125e-07f);
    for (int i = threadIdx.x; i < CC; i += 256) {
        float u = p[i] * inv;
        __nv_bfloat16 hh, ll;
        split2(u, hh, ll);
        ynh[(size_t)row * CC + i] = hh;
        ynl[(size_t)row * CC + i] = ll;
    }
}

// ---------------- host driver -----------------------------------------------------
#define SYM(p, s) cudaGetSymbolAddress((void**)&p, s)

extern "C" void kernel_launch(void* const* d_in, const int* in_sizes, int n_in,
                              void* d_out, int out_size)
{
    const float* x     = (const float*)d_in[0];
    const float* Wq    = (const float*)d_in[1];
    const float* Wk    = (const float*)d_in[2];
    const float* Wv    = (const float*)d_in[3];
    const float* Wm1   = (const float*)d_in[4];
    const float* bm1   = (const float*)d_in[5];
    const float* Wm2   = (const float*)d_in[6];
    const float* bm2   = (const float*)d_in[7];
    const float* Wproj = (const float*)d_in[8];
    const float* Wfc   = (const float*)d_in[9];
    const float* Wcp   = (const float*)d_in[10];
    float* out = (float*)d_out;

    float *pqkv, *ph, *psur, *py;
    __nv_bfloat16 *pxh, *pxl, *pysh, *pysl, *pynh, *pynl, *pffh, *pffl;
    __nv_bfloat16 *pWqkvh, *pWqkvl, *pWm1h, *pWm1l;
    __nv_bfloat16 *pWph, *pWpl, *pWfh, *pWfl, *pWch, *pWcl;

    SYM(pqkv, g_qkv); SYM(ph, g_h); SYM(psur, g_sur); SYM(py, g_y);
    SYM(pxh, g_xh); SYM(pxl, g_xl);
    SYM(pysh, g_ysh); SYM(pysl, g_ysl);
    SYM(pynh, g_ynh); SYM(pynl, g_ynl);
    SYM(pffh, g_ffh); SYM(pffl, g_ffl);
    SYM(pWqkvh, g_Wqkvh); SYM(pWqkvl, g_Wqkvl);
    SYM(pWm1h, g_Wm1h); SYM(pWm1l, g_Wm1l);
    SYM(pWph, g_Wph); SYM(pWpl, g_Wpl);
    SYM(pWfh, g_Wfh); SYM(pWfl, g_Wfl);
    SYM(pWch, g_Wch); SYM(pWcl, g_Wcl);

    cudaFuncSetAttribute(bf16_gemm<0,0>, cudaFuncAttributeMaxDynamicSharedMemorySize, SMEM_BYTES);
    cudaFuncSetAttribute(bf16_gemm<1,0>, cudaFuncAttributeMaxDynamicSharedMemorySize, SMEM_BYTES);
    cudaFuncSetAttribute(bf16_gemm<2,1>, cudaFuncAttributeMaxDynamicSharedMemorySize, SMEM_BYTES);
    cudaFuncSetAttribute(bf16_gemm<3,0>, cudaFuncAttributeMaxDynamicSharedMemorySize, SMEM_BYTES);

    auto splits = [&](const float* s, __nv_bfloat16* h, __nv_bfloat16* l, int n) {
        split_kernel<<<(n / 2 + 255) / 256, 256>>>(s, h, l, n / 2);
    };

    dim3 thr(256);
    dim3 gQKV(C3  / BNW, MM / BM);   // 24 x 32 = 768 CTAs
    dim3 gC  (CC  / BNW, MM / BM);
    dim3 gH  (HID / BNW, MM / BM);
    dim3 gFF (FF  / BNW, MM / BM);

    // Launches 0-4: splits needed for QKV+meta (keeps launch idx 5 = big GEMM for ncu)
    splits(x,   pxh, pxl, MM * CC);                       // 0
    splits(Wq,  pWqkvh,              pWqkvl,              CC * CC);  // 1
    splits(Wk,  pWqkvh + CC * CC,    pWqkvl + CC * CC,    CC * CC);  // 2
    splits(Wv,  pWqkvh + 2 * CC * CC, pWqkvl + 2 * CC * CC, CC * CC); // 3
    splits(Wm1, pWm1h, pWm1l, HID * CC);                  // 4

    // 5: fused QKV projection -> qkv fp32 (profiled by ncu -s 5 -c 1)
    bf16_gemm<0,0><<<gQKV, thr, SMEM_BYTES>>>(pxh, pxl, pWqkvh, pWqkvl, nullptr, nullptr,
                                              pqkv, nullptr, nullptr, MM, C3, CC);

    // meta net
    bf16_gemm<1,0><<<gH, thr, SMEM_BYTES>>>(pxh, pxl, pWm1h, pWm1l, bm1, nullptr,
                                            ph, nullptr, nullptr, MM, HID, CC);
    meta2_kernel<<<(MM * HH + 255) / 256, thr>>>(ph, Wm2, bm2, psur);

    // gated linear-attention scan -> ys (bf16 hi/lo)
    scan_kernel<<<BB * HH * 2, 256>>>(pqkv, psur, pysh, pysl);

    // remaining weight splits
    splits(Wproj, pWph, pWpl, CC * CC);
    splits(Wfc,   pWfh, pWfl, FF * CC);
    splits(Wcp,   pWch, pWcl, CC * FF);

    // output projection (fp32 y, needed for residual)
    bf16_gemm<0,0><<<gC, thr, SMEM_BYTES>>>(pysh, pysl, pWph, pWpl, nullptr, nullptr,
                                            py, nullptr, nullptr, MM, CC, CC);

    // RMSNorm -> yn (bf16 hi/lo)
    rmsnorm_kernel<<<MM, thr>>>(py, pynh, pynl);

    // MLP: ff = relu(yn Wfc^T)^2 (bf16 hi/lo) ; out = y + ff Wcp^T (fp32)
    bf16_gemm<2,1><<<gFF, thr, SMEM_BYTES>>>(pynh, pynl, pWfh, pWfl, nullptr, nullptr,
                                             nullptr, pffh, pffl, MM, FF, CC);
    bf16_gemm<3,0><<<gC, thr, SMEM_BYTES>>>(pffh, pffl, pWch, pWcl, nullptr, py,
                                            out, nullptr, nullptr, MM, CC, FF);
}